// round 10
// baseline (speedup 1.0000x reference)
#include <cuda_runtime.h>
#include <cuda_fp16.h>
#include <cstdint>

#define NC   3144   // counties
#define TT   156    // time steps
#define TP   154    // predicted steps (T - p)
#define TPAD 160    // padded t dimension
#define NNZ  31440
#define CAP  128    // bucket capacity (Poisson(10), max ~35)

#define NMT  99     // m-tiles of 32 for the transpose
#define K1_SCAT  123                    // ceil(NNZ/256)
#define K1_TRANS (NMT * 5)              // 495
#define K1_BASE  (13 * 20)              // 260: 13 m-groups x 20 t-chunks
#define K1_BLOCKS (K1_SCAT + K1_TRANS + K1_BASE)

// ---- scratch (zero-initialized at load; meta slots >= cnt stay zero) ----
__device__ int     g_count[NC];
__device__ int4    g_meta[NC * CAP];  // {row, bv, av, hv}; pad slots = 0
__device__ __half2 g_csdh[NC * TPAD]; // {cs, ds} fp16 at [m][t]

// ============================================================
// Kernel 1 (256 thr): scatter (123) + csdh transpose (495) +
// mobility/covariate base written DIRECTLY to out (260).
// ============================================================
__global__ void k1_kernel(
    const float* __restrict__ C, const float* __restrict__ D,
    const float* __restrict__ M, const float* __restrict__ cov,
    const float* __restrict__ mu, const float* __restrict__ nu,
    const float* __restrict__ ups, const float* __restrict__ zeta,
    const float* __restrict__ bnz, const float* __restrict__ anz,
    const float* __restrict__ hnz, const int* __restrict__ rows,
    const int* __restrict__ cols, float* __restrict__ out)
{
    const int b = blockIdx.x, tid = threadIdx.x;

    // ---------------- scatter ----------------
    if (b < K1_SCAT) {
        int k = b * 256 + tid;
        if (k < NNZ) {
            int c = cols[k];
            int slot = atomicAdd(&g_count[c], 1);
            if (slot < CAP)
                g_meta[c * CAP + slot] = make_int4(
                    rows[k], __float_as_int(bnz[k]),
                    __float_as_int(anz[k]), __float_as_int(hnz[k]));
        }
        return;
    }

    // ---------------- C/D lag-sum transpose -> fp16 [m][t] ----------------
    if (b < K1_SCAT + K1_TRANS) {
        __shared__ float sC[33][33], sD[33][33];
        const int tb = b - K1_SCAT;
        const int m0 = (tb % NMT) * 32, t0 = (tb / NMT) * 32;

        for (int idx = tid; idx < 33 * 32; idx += 256) {
            int r = idx >> 5, cm = idx & 31;
            int tg = min(t0 + r, TT - 1);
            int mg = min(m0 + cm, NC - 1);
            sC[r][cm] = C[tg * NC + mg];
            sD[r][cm] = D[tg * NC + mg];
        }
        __syncthreads();

        const int tx = tid & 31, ty = tid >> 5;   // tx = t offset
#pragma unroll
        for (int i = 0; i < 4; i++) {
            int ml = ty * 4 + i;
            int mg = m0 + ml;
            if (mg < NC) {
                float cs = sC[tx][ml] + sC[tx + 1][ml];
                float ds = sD[tx][ml] + sD[tx + 1][ml];
                g_csdh[mg * TPAD + t0 + tx] = __floats2half2_rn(cs, ds);
            }
        }
        return;
    }

    // ---------------- base: mobility + covariate -> out ----------------
    {
        const int bb = b - K1_SCAT - K1_TRANS;
        const int mgrp = bb % 13, chunk = bb / 13;
        const int m = mgrp * 256 + tid;
        if (m >= NC) return;
        const int t0 = chunk * 8;

        float cc = 0.f, cd = 0.f;
#pragma unroll
        for (int j = 0; j < 10; j++) {
            float cvv = cov[j * NC + m];
            cc += ups[j]  * cvv;
            cd += zeta[j] * cvv;
        }

        float muv[12], nuv[12];
#pragma unroll
        for (int i = 0; i < 12; i++) { muv[i] = mu[i]; nuv[i] = nu[i]; }

        float mn[6];
#pragma unroll
        for (int k = 0; k < 6; k++) mn[k] = M[(k * TT + t0) * NC + m];

#pragma unroll
        for (int j = 0; j < 8; j++) {
            int t = t0 + j;
            int tn = min(t + 1, TT - 1);
            float mc = cc, md = cd;
#pragma unroll
            for (int k = 0; k < 6; k++) {
                float v0 = mn[k];
                float v1 = M[(k * TT + tn) * NC + m];
                mn[k] = v1;
                mc += muv[k*2] * v0 + muv[k*2+1] * v1;
                md += nuv[k*2] * v0 + nuv[k*2+1] * v1;
            }
            if (t < TP) {
                out[t        * NC + m] = mc;
                out[(TP + t) * NC + m] = md;
            }
        }
    }
}

// ============================================================
// Kernel 2 (256 thr, 393 blocks): pure sparse gather.
// Warp = one column m over all 160 t (5 half2 cells per lane).
// nnz count padded to multiple of 4 -> straight-line 20-load
// batches. Epilogue: coalesced RMW on out (adds to base).
// ============================================================
__global__ void k2_kernel(float* __restrict__ out)
{
    __shared__ int4   smeta[8][32];
    __shared__ float2 tile[TPAD][9];      // [t][m_local], padded

    const int tid  = threadIdx.x;
    const int w    = tid >> 5, lane = tid & 31;
    const int m0   = blockIdx.x * 8;
    const int m    = m0 + w;              // NC = 393*8 exact

    // meta: one coalesced int4 lane-load covers 32 slots
    smeta[w][lane] = g_meta[m * CAP + lane];
    const int cnt = g_count[m];           // broadcast
    __syncwarp();
    if (lane == 0) g_count[m] = 0;        // re-arm for graph replay

    float accC[5] = {0.f, 0.f, 0.f, 0.f, 0.f};
    float accD[5] = {0.f, 0.f, 0.f, 0.f, 0.f};

    const __half2* __restrict__ csd = g_csdh;
    const int jn = min((cnt + 3) & ~3, 32);   // pad: slots >= cnt are zero

    for (int j = 0; j < jn; j += 4) {
        int4 mda = smeta[w][j];
        int4 mdb = smeta[w][j + 1];
        int4 mdc = smeta[w][j + 2];
        int4 mdd = smeta[w][j + 3];
        const __half2* ra = &csd[mda.x * TPAD + lane];
        const __half2* rb = &csd[mdb.x * TPAD + lane];
        const __half2* rc = &csd[mdc.x * TPAD + lane];
        const __half2* rd = &csd[mdd.x * TPAD + lane];
        __half2 va[5], vb[5], vc[5], vd[5];
#pragma unroll
        for (int i = 0; i < 5; i++) {     // 20 independent loads, one batch
            va[i] = ra[32 * i];
            vb[i] = rb[32 * i];
            vc[i] = rc[32 * i];
            vd[i] = rd[32 * i];
        }
        float ba = __int_as_float(mda.y), aa = __int_as_float(mda.z), ha = __int_as_float(mda.w);
        float bb = __int_as_float(mdb.y), ab = __int_as_float(mdb.z), hb = __int_as_float(mdb.w);
        float bc = __int_as_float(mdc.y), ac = __int_as_float(mdc.z), hc = __int_as_float(mdc.w);
        float bd = __int_as_float(mdd.y), ad = __int_as_float(mdd.z), hd = __int_as_float(mdd.w);
#pragma unroll
        for (int i = 0; i < 5; i++) {
            float2 pa = __half22float2(va[i]);
            float2 pb = __half22float2(vb[i]);
            float2 pc = __half22float2(vc[i]);
            float2 pd = __half22float2(vd[i]);
            accC[i] += ba * pa.x + bb * pb.x + bc * pc.x + bd * pd.x;
            accD[i] += ha * pa.x + aa * pa.y
                     + hb * pb.x + ab * pb.y
                     + hc * pc.x + ac * pc.y
                     + hd * pd.x + ad * pd.y;
        }
    }
    // rare tail (cnt > 32)
    for (int s = 32; s < cnt; s++) {
        int4 md = g_meta[m * CAP + s];
        const __half2* rr = &csd[md.x * TPAD + lane];
        float bv = __int_as_float(md.y);
        float av = __int_as_float(md.z);
        float hv = __int_as_float(md.w);
#pragma unroll
        for (int i = 0; i < 5; i++) {
            float2 p = __half22float2(rr[32 * i]);
            accC[i] += bv * p.x;
            accD[i] += hv * p.x + av * p.y;
        }
    }

    // transpose through smem
#pragma unroll
    for (int i = 0; i < 5; i++)
        tile[lane + 32 * i][w] = make_float2(accC[i], accD[i]);
    __syncthreads();

    // coalesced RMW: out already holds the base terms from k1
#pragma unroll
    for (int i = 0; i < 10; i++) {
        int idx = tid + i * 256;          // < 2560
        int t = idx >> 3, mo = idx & 7;
        if (t < TP) {
            float2 v = tile[t][mo];
            out[t        * NC + m0 + mo] += v.x;
            out[(TP + t) * NC + m0 + mo] += v.y;
        }
    }
}

// ============================================================
extern "C" void kernel_launch(void* const* d_in, const int* in_sizes, int n_in,
                              void* d_out, int out_size)
{
    const float* C    = (const float*)d_in[0];
    const float* D    = (const float*)d_in[1];
    const float* M    = (const float*)d_in[2];
    const float* cov  = (const float*)d_in[3];
    const float* bnz  = (const float*)d_in[4];
    const float* anz  = (const float*)d_in[5];
    const float* hnz  = (const float*)d_in[6];
    const float* mu   = (const float*)d_in[7];
    const float* nu   = (const float*)d_in[8];
    const float* ups  = (const float*)d_in[9];
    const float* zeta = (const float*)d_in[10];
    const int*   rows = (const int*)d_in[11];
    const int*   cols = (const int*)d_in[12];
    float* out = (float*)d_out;

    k1_kernel<<<K1_BLOCKS, 256>>>(C, D, M, cov, mu, nu, ups, zeta,
                                  bnz, anz, hnz, rows, cols, out);
    k2_kernel<<<NC / 8, 256>>>(out);
}